// round 6
// baseline (speedup 1.0000x reference)
#include <cuda_runtime.h>
#include <cuda_fp16.h>
#include <math.h>
#include <stdint.h>

// ---------------- problem constants ----------------
#define NB1 8192
#define NB2 8192
#define ND  128

// ---------------- screen tiling ----------------
#define BM 128
#define BN 64
#define SPLITC 16
#define COLS_PER_CTA (NB2 / SPLITC)          // 512
#define TILES (COLS_PER_CTA / BN)            // 8

// candidate collection
#define CAP 24
#define DELTA 0.25f

// smem map: Ah 32KB | Bh ring 3 x 16KB | n2 2KB | rowmin 512B
#define SMEM_A 0
#define SMEM_B 32768
#define BSTAGE 16384
#define SMEM_N2 (SMEM_B + 3 * BSTAGE)        // 81920
#define SMEM_RMIN (SMEM_N2 + 2048)           // 83968
#define SMEM_BYTES (SMEM_RMIN + 512)         // 84480  (2 CTAs/SM)

#define SW128(o) ((o) ^ (((o) >> 3) & 0x70))

// ---------------- scratch globals ----------------
__device__ __align__(16) float  g_n1[NB1];
__device__ __align__(16) float  g_n2[NB2];
__device__ __align__(16) __half g_Ah[NB1 * ND];
__device__ __align__(16) __half g_Bh[NB2 * ND];
__device__ unsigned g_ccnt[NB1 * SPLITC];
__device__ __align__(16) float2 g_cand[(size_t)NB1 * SPLITC * CAP];

// ---------------- PTX helpers (portable sm_80-level only) ----------------
__device__ __forceinline__ uint32_t smem_u32(const void* p) {
    uint32_t a;
    asm("{ .reg .u64 t; cvta.to.shared.u64 t, %1; cvt.u32.u64 %0, t; }" : "=r"(a) : "l"(p));
    return a;
}
#define CP_ASYNC16(dst, src) \
    asm volatile("cp.async.cg.shared.global [%0], [%1], 16;" :: "r"(dst), "l"(src) : "memory")
#define CP_COMMIT() asm volatile("cp.async.commit_group;" ::: "memory")
#define CP_WAIT1()  asm volatile("cp.async.wait_group 1;" ::: "memory")

#define LDMATRIX_X4(r0, r1, r2, r3, addr) \
    asm volatile("ldmatrix.sync.aligned.m8n8.x4.shared.b16 {%0,%1,%2,%3}, [%4];" \
        : "=r"(r0), "=r"(r1), "=r"(r2), "=r"(r3) : "r"(addr))

#define MMA16816(acc, a, b0v, b1v) \
    asm volatile("mma.sync.aligned.m16n8k16.row.col.f32.f16.f16.f32 " \
        "{%0,%1,%2,%3}, {%4,%5,%6,%7}, {%8,%9}, {%0,%1,%2,%3};" \
        : "+f"((acc)[0]), "+f"((acc)[1]), "+f"((acc)[2]), "+f"((acc)[3]) \
        : "r"((a)[0]), "r"((a)[1]), "r"((a)[2]), "r"((a)[3]), "r"(b0v), "r"(b1v))

// monotone float <-> unsigned encoding (for atomicMin over possibly-negative v)
__device__ __forceinline__ unsigned fenc(float f) {
    unsigned u = __float_as_uint(f);
    return (u & 0x80000000u) ? ~u : (u | 0x80000000u);
}
__device__ __forceinline__ float fdec(unsigned u) {
    return (u & 0x80000000u) ? __uint_as_float(u & 0x7FFFFFFFu)
                             : __uint_as_float(~u);
}

// ---------------------------------------------------------------------------
// Kernel 0: fp16 hi conversion + squared norms + zero candidate counters.
// ---------------------------------------------------------------------------
__global__ void prep_kernel(const float* __restrict__ d1,
                            const float* __restrict__ d2) {
    int gid  = blockIdx.x * blockDim.x + threadIdx.x;
    int warp = gid >> 5;
    int lane = threadIdx.x & 31;
    if (gid < NB1 * SPLITC) g_ccnt[gid] = 0;
    if (warp >= NB1 + NB2) return;
    bool isB = (warp >= NB1);
    int row = isB ? warp - NB1 : warp;
    const float* src = (isB ? d2 : d1) + (size_t)row * ND;
    float4 v = ((const float4*)src)[lane];

    float s = v.x * v.x + v.y * v.y + v.z * v.z + v.w * v.w;
    #pragma unroll
    for (int o = 16; o; o >>= 1) s += __shfl_xor_sync(0xffffffffu, s, o);
    if (lane == 0) {
        if (isB) g_n2[row] = s;
        else     g_n1[row] = s;
    }

    __half2 h01 = __halves2half2(__float2half_rn(v.x), __float2half_rn(v.y));
    __half2 h23 = __halves2half2(__float2half_rn(v.z), __float2half_rn(v.w));
    uint2 hp = make_uint2(*(uint32_t*)&h01, *(uint32_t*)&h23);
    ((uint2*)(isB ? g_Bh : g_Ah))[(size_t)row * 32 + lane] = hp;
}

// ---------------------------------------------------------------------------
// smem loaders (SW128-swizzled K-major tiles)
// ---------------------------------------------------------------------------
__device__ __forceinline__ void load_a_panel(uint32_t dstbase, int row0, int tid) {
    #pragma unroll
    for (int g = 0; g < 8; g++) {
        int idx = g * 256 + tid;            // 2048 granules
        int chunk = idx >> 10;
        int rem   = idx & 1023;
        int row   = rem >> 3;
        int gi    = rem & 7;
        const __half* src = g_Ah + (size_t)(row0 + row) * ND + chunk * 64 + gi * 8;
        CP_ASYNC16(dstbase + chunk * 16384 + SW128(row * 128 + gi * 16), src);
    }
}
__device__ __forceinline__ void load_b_stage(uint32_t dstbase, int col0, int tid) {
    #pragma unroll
    for (int g = 0; g < 4; g++) {
        int idx = g * 256 + tid;            // 1024 granules
        int chunk = idx >> 9;
        int rem   = idx & 511;
        int row   = rem >> 3;
        int gi    = rem & 7;
        const __half* src = g_Bh + (size_t)(col0 + row) * ND + chunk * 64 + gi * 8;
        CP_ASYNC16(dstbase + chunk * 8192 + SW128(row * 128 + gi * 16), src);
    }
}

// ---------------------------------------------------------------------------
// Kernel 1 (screen): hi-only mma.sync GEMM + running-min candidate collection
// 256 threads = 8 warps (4 row x 2 col); warp tile 32x32.
// ---------------------------------------------------------------------------
struct FragsH { uint32_t aH[2][4], bH[2][4]; };
__device__ __forceinline__ void load_frags(
    FragsH& f, uint32_t abase, uint32_t bbase, int ks,
    int wrow, int wcol, int a_rl, int a_koff, int b_nl, int b_koff)
{
    #pragma unroll
    for (int m = 0; m < 2; m++) {
        int row = wrow + m * 16 + a_rl;
        int kb  = ks * 16 + a_koff;
        uint32_t addr = abase + (kb >> 6) * 16384 + row * 128 +
                        (((kb & 63) * 2) ^ ((row & 7) << 4));
        LDMATRIX_X4(f.aH[m][0], f.aH[m][1], f.aH[m][2], f.aH[m][3], addr);
    }
    #pragma unroll
    for (int pr = 0; pr < 2; pr++) {
        int nrow = wcol + pr * 16 + b_nl;
        int kb   = ks * 16 + b_koff;
        uint32_t addr = bbase + (kb >> 6) * 8192 + nrow * 128 +
                        (((kb & 63) * 2) ^ ((nrow & 7) << 4));
        LDMATRIX_X4(f.bH[pr][0], f.bH[pr][1], f.bH[pr][2], f.bH[pr][3], addr);
    }
}

__global__ void __launch_bounds__(256, 2)
screen_kernel() {
    extern __shared__ char smem[];
    const uint32_t sbase = smem_u32(smem);
    const int tid  = threadIdx.x;
    const int lane = tid & 31;
    const int warp = tid >> 5;
    const int wrow = (warp >> 1) * 32;
    const int wcol = (warp & 1) * 32;
    const int rowBase = blockIdx.x * BM;
    const int split   = blockIdx.y;
    const int colBase = split * COLS_PER_CTA;

    const int a_rl   = lane & 15;
    const int a_koff = (lane >> 4) * 8;
    const int b_nl   = (lane & 7) + (lane >> 4) * 8;
    const int b_koff = ((lane >> 3) & 1) * 8;

    unsigned* rmin = (unsigned*)(smem + SMEM_RMIN);
    if (tid < BM) rmin[tid] = 0xFFFFFFFFu;

    // ---- prologue: A panel + n2 + first two B stages ----
    load_a_panel(sbase + SMEM_A, rowBase, tid);
    if (tid < 128)
        CP_ASYNC16(sbase + SMEM_N2 + tid * 16, g_n2 + colBase + tid * 4);
    load_b_stage(sbase + SMEM_B + 0 * BSTAGE, colBase + 0 * BN, tid);
    CP_COMMIT();
    load_b_stage(sbase + SMEM_B + 1 * BSTAGE, colBase + 1 * BN, tid);
    CP_COMMIT();

    const float* n2s = (const float*)(smem + SMEM_N2);

    for (int i = 0; i < TILES; i++) {
        CP_WAIT1();
        __syncthreads();

        if (i + 2 < TILES)
            load_b_stage(sbase + SMEM_B + ((i + 2) % 3) * BSTAGE,
                         colBase + (i + 2) * BN, tid);
        CP_COMMIT();

        const uint32_t abase = sbase + SMEM_A;
        const uint32_t bbase = sbase + SMEM_B + (i % 3) * BSTAGE;

        float acc[2][4][4];
        #pragma unroll
        for (int m = 0; m < 2; m++)
            #pragma unroll
            for (int n = 0; n < 4; n++)
                #pragma unroll
                for (int c = 0; c < 4; c++) acc[m][n][c] = 0.0f;

        FragsH fr[2];
        load_frags(fr[0], abase, bbase, 0, wrow, wcol, a_rl, a_koff, b_nl, b_koff);
        #pragma unroll
        for (int ks = 0; ks < 8; ks++) {
            const int cur = ks & 1;
            if (ks < 7)
                load_frags(fr[cur ^ 1], abase, bbase, ks + 1,
                           wrow, wcol, a_rl, a_koff, b_nl, b_koff);
            FragsH& f = fr[cur];
            #pragma unroll
            for (int m = 0; m < 2; m++) {
                MMA16816(acc[m][0], f.aH[m], f.bH[0][0], f.bH[0][1]);
                MMA16816(acc[m][1], f.aH[m], f.bH[0][2], f.bH[0][3]);
                MMA16816(acc[m][2], f.aH[m], f.bH[1][0], f.bH[1][1]);
                MMA16816(acc[m][3], f.aH[m], f.bH[1][2], f.bH[1][3]);
            }
        }

        // ---- epilogue: v = n2 - 2*dot, per-row running min, collect ----
        const int cloc = i * BN + wcol;
        float n2v[8];
        #pragma unroll
        for (int n = 0; n < 4; n++) {
            n2v[n * 2]     = n2s[cloc + n * 8 + (lane & 3) * 2];
            n2v[n * 2 + 1] = n2s[cloc + n * 8 + (lane & 3) * 2 + 1];
        }

        float smin[4] = {3.4e38f, 3.4e38f, 3.4e38f, 3.4e38f};
        #pragma unroll
        for (int m = 0; m < 2; m++)
            #pragma unroll
            for (int n = 0; n < 4; n++)
                #pragma unroll
                for (int c = 0; c < 4; c++) {
                    float v = n2v[n * 2 + (c & 1)] - 2.0f * acc[m][n][c];
                    acc[m][n][c] = v;
                    int s = m * 2 + (c >> 1);
                    smin[s] = fminf(smin[s], v);
                }

        #pragma unroll
        for (int s = 0; s < 4; s++) {
            float v2 = smin[s];
            v2 = fminf(v2, __shfl_xor_sync(0xffffffffu, v2, 1));
            v2 = fminf(v2, __shfl_xor_sync(0xffffffffu, v2, 2));
            if ((lane & 3) == 0)
                atomicMin(&rmin[wrow + (s >> 1) * 16 + (s & 1) * 8 + (lane >> 2)],
                          fenc(v2));
        }
        __syncthreads();   // rmin now includes ALL of tile i

        float thr_s[4];
        #pragma unroll
        for (int s = 0; s < 4; s++)
            thr_s[s] = fdec(rmin[wrow + (s >> 1) * 16 + (s & 1) * 8 + (lane >> 2)])
                       + DELTA;

        const int c0 = colBase + i * BN + wcol;
        #pragma unroll
        for (int m = 0; m < 2; m++)
            #pragma unroll
            for (int n = 0; n < 4; n++)
                #pragma unroll
                for (int c = 0; c < 4; c++) {
                    int s = m * 2 + (c >> 1);
                    float v = acc[m][n][c];
                    if (v < thr_s[s]) {
                        int rl  = wrow + m * 16 + (c >> 1) * 8 + (lane >> 2);
                        int col = c0 + n * 8 + (lane & 3) * 2 + (c & 1);
                        int gr  = rowBase + rl;
                        unsigned slot = atomicAdd(&g_ccnt[gr * SPLITC + split], 1u);
                        if (slot < CAP)
                            g_cand[((size_t)gr * SPLITC + split) * CAP + slot] =
                                make_float2(v, __int_as_float(col));
                    }
                }
    }
}

// ---------------------------------------------------------------------------
// Kernel 2 (rescore): warp per row. Find screened min over candidates, then
// exact fp32 rescore of survivors (v <= min + DELTA); tie-break lowest index.
// ---------------------------------------------------------------------------
__global__ void rescore_kernel(const float* __restrict__ d1,
                               const float* __restrict__ d2,
                               float* __restrict__ out) {
    int warp = (blockIdx.x * blockDim.x + threadIdx.x) >> 5;
    int lane = threadIdx.x & 31;
    if (warp >= NB1) return;
    const int row = warp;

    float4 a4 = ((const float4*)(d1 + (size_t)row * ND))[lane];
    float n1r = g_n1[row];

    // phase 1: screened minimum over all stored candidates
    float m = 3.4e38f;
    if (lane < SPLITC) {
        unsigned n = g_ccnt[row * SPLITC + lane];
        if (n > CAP) n = CAP;
        size_t base = ((size_t)row * SPLITC + lane) * CAP;
        for (unsigned k = 0; k < n; k++)
            m = fminf(m, g_cand[base + k].x);
    }
    #pragma unroll
    for (int o = 16; o; o >>= 1)
        m = fminf(m, __shfl_xor_sync(0xffffffffu, m, o));
    const float thr = m + DELTA;

    // phase 2: exact rescore of survivors
    float bv = 3.4e38f;
    int   bj = 0x7fffffff;
    for (int sp = 0; sp < SPLITC; sp++) {
        unsigned n = g_ccnt[row * SPLITC + sp];
        if (n > CAP) n = CAP;
        size_t base = ((size_t)row * SPLITC + sp) * CAP;
        for (unsigned k = 0; k < n; k++) {
            float2 cd = g_cand[base + k];      // uniform across warp
            if (cd.x <= thr) {
                int j = __float_as_int(cd.y);
                float4 b4 = ((const float4*)(d2 + (size_t)j * ND))[lane];
                float d = a4.x * b4.x + a4.y * b4.y + a4.z * b4.z + a4.w * b4.w;
                #pragma unroll
                for (int o = 16; o; o >>= 1)
                    d += __shfl_xor_sync(0xffffffffu, d, o);
                float v = n1r + g_n2[j] - 2.0f * d;
                if (v < bv || (v == bv && j < bj)) { bv = v; bj = j; }
            }
        }
    }

    if (lane == 0) {
        out[row] = sqrtf(fmaxf(bv, 0.0f));
        out[NB1 + 2 * row]     = (float)row;
        out[NB1 + 2 * row + 1] = (float)bj;
    }
}

// ---------------------------------------------------------------------------
extern "C" void kernel_launch(void* const* d_in, const int* in_sizes, int n_in,
                              void* d_out, int out_size) {
    const float* d1 = (const float*)d_in[0];
    const float* d2 = (const float*)d_in[1];
    float* out = (float*)d_out;

    cudaFuncSetAttribute(screen_kernel,
                         cudaFuncAttributeMaxDynamicSharedMemorySize, SMEM_BYTES);

    prep_kernel<<<(NB1 + NB2) / 8, 256>>>(d1, d2);
    screen_kernel<<<dim3(NB1 / BM, SPLITC), 256, SMEM_BYTES>>>();
    rescore_kernel<<<NB1 / 8, 256>>>(d1, d2, out);
}